// round 15
// baseline (speedup 1.0000x reference)
#include <cuda_runtime.h>

#define TT   512
#define BB   64
#define HH   512
#define G4   2048
#define MS   300
#define INW  812
#define NBLK 128
#define BQ_F 33280              /* 832 k x 40 n resident weight smem (floats) */
#define PIT  132                /* A-chunk row pitch (floats)                 */
#define ABUF (64*PIT)           /* floats per A chunk buffer                  */
#define DYN_BYTES ((BQ_F + 2*ABUF)*4)

#define XAP  36
#define XBP  72
#define XAS  (128*XAP)
#define XBS  (32*XBP)
#define XP_SMEM ((2*XAS + 2*XBS)*4)

// ---------------- device scratch ----------------
__device__ float d_Xp[2][TT * BB][G4];
__device__ float d_hbuf[2][2][BB][HH];      // h, tf32-rounded at producer
__device__ float d_expl[2][BB][320];        // exp(logits), batch-major, tf32, zero-padded
__device__ float d_Pt[2][G4][320];
__device__ unsigned d_flag[NBLK * 32];      // per-block epoch flags, 128B apart

__global__ void reset_kernel() {
    int i = blockIdx.x * blockDim.x + threadIdx.x;
    int n = gridDim.x * blockDim.x;
    for (int x = i; x < NBLK * 32; x += n) d_flag[x] = 0u;
    float* e = &d_expl[0][0][0];
    for (int x = i; x < 2 * BB * 320; x += n) e[x] = 0.0f;
}

__device__ __forceinline__ float f2tf(float f) {
    unsigned u; asm("cvt.rna.tf32.f32 %0, %1;" : "=r"(u) : "f"(f));
    return __uint_as_float(u);
}
__device__ __forceinline__ void mma8(float* d, unsigned a0, unsigned a1,
    unsigned a2, unsigned a3, unsigned b0, unsigned b1) {
    asm volatile("mma.sync.aligned.m16n8k8.row.col.f32.tf32.tf32.f32 "
        "{%0,%1,%2,%3},{%4,%5,%6,%7},{%8,%9},{%0,%1,%2,%3};"
        : "+f"(d[0]), "+f"(d[1]), "+f"(d[2]), "+f"(d[3])
        : "r"(a0), "r"(a1), "r"(a2), "r"(a3), "r"(b0), "r"(b1));
}
__device__ __forceinline__ void cpa16(unsigned dst, const void* src) {
    asm volatile("cp.async.cg.shared.global [%0], [%1], 16;" :: "r"(dst), "l"(src));
}
#define CPA_COMMIT() asm volatile("cp.async.commit_group;")
template <int N> __device__ __forceinline__ void cpa_wait() {
    asm volatile("cp.async.wait_group %0;" :: "n"(N));
}
__device__ __forceinline__ unsigned ld_acq(const unsigned* p) {
    unsigned v;
    asm volatile("ld.acquire.gpu.global.u32 %0, [%1];" : "=r"(v) : "l"(p));
    return v;
}
__device__ __forceinline__ void st_rel_exch(unsigned* p, unsigned v) {
    unsigned old;
    asm volatile("atom.release.gpu.global.exch.b32 %0, [%1], %2;"
                 : "=r"(old) : "l"(p), "r"(v) : "memory");
}

// ---------------- xproj via tf32 MMA (unchanged) ----------------
__global__ void __launch_bounds__(256, 1) xproj_mma(
    const float* __restrict__ seqs,
    const float* __restrict__ Wih_f, const float* __restrict__ Wih_b,
    const float* __restrict__ bih_f, const float* __restrict__ bhh_f,
    const float* __restrict__ bih_b, const float* __restrict__ bhh_b)
{
    extern __shared__ float xs[];
    float* As = xs;
    float* Bs = xs + 2 * XAS;

    const int d  = blockIdx.z;
    const float* W  = d ? Wih_b : Wih_f;
    const float* bi = d ? bih_b : bih_f;
    const float* bh = d ? bhh_b : bhh_f;
    const int n0 = blockIdx.x * 64;
    const int m0 = blockIdx.y * 128;

    const int tid  = threadIdx.x;
    const int w    = tid >> 5, lane = tid & 31;
    const int gid  = lane >> 2, t4 = lane & 3;
    const int wm   = w & 3, wn = w >> 2;

    const int ar = tid >> 1;
    const int ak = (tid & 1) * 16;
    const int grow = m0 + ar;
    const int att  = grow >> 6;
    const int abb  = grow & 63;
    const int tsrc = d ? (TT - 1 - att) : att;
    const float* aptr = seqs + ((size_t)abb * TT + tsrc) * HH + ak;

    const int bn = tid >> 2;
    const int bk = (tid & 3) * 4;
    const float* bptr = W + (size_t)(n0 + bn) * INW + bk;

    float acc[2][4][4];
#pragma unroll
    for (int mt = 0; mt < 2; ++mt)
#pragma unroll
        for (int nt = 0; nt < 4; ++nt)
#pragma unroll
            for (int i = 0; i < 4; ++i) acc[mt][nt][i] = 0.0f;

    float4 av[4], bv[2];
#pragma unroll
    for (int q = 0; q < 4; ++q) av[q] = *(const float4*)(aptr + q * 4);
    bv[0] = *(const float4*)(bptr);
    bv[1] = *(const float4*)(bptr + 16);
    {
        float* A0 = As; float* B0 = Bs;
#pragma unroll
        for (int q = 0; q < 4; ++q) {
            float4 sv;
            sv.x = f2tf(av[q].x); sv.y = f2tf(av[q].y);
            sv.z = f2tf(av[q].z); sv.w = f2tf(av[q].w);
            *(float4*)(A0 + ar * XAP + ak + q * 4) = sv;
        }
        B0[(bk + 0) * XBP + bn] = f2tf(bv[0].x);
        B0[(bk + 1) * XBP + bn] = f2tf(bv[0].y);
        B0[(bk + 2) * XBP + bn] = f2tf(bv[0].z);
        B0[(bk + 3) * XBP + bn] = f2tf(bv[0].w);
        B0[(16 + bk + 0) * XBP + bn] = f2tf(bv[1].x);
        B0[(16 + bk + 1) * XBP + bn] = f2tf(bv[1].y);
        B0[(16 + bk + 2) * XBP + bn] = f2tf(bv[1].z);
        B0[(16 + bk + 3) * XBP + bn] = f2tf(bv[1].w);
    }
    __syncthreads();

#pragma unroll 1
    for (int kt = 0; kt < 16; ++kt) {
        if (kt < 15) {
            int k0 = (kt + 1) * 32;
#pragma unroll
            for (int q = 0; q < 4; ++q) av[q] = *(const float4*)(aptr + k0 + q * 4);
            bv[0] = *(const float4*)(bptr + k0);
            bv[1] = *(const float4*)(bptr + k0 + 16);
        }
        const float* A = As + (kt & 1) * XAS;
        const float* B = Bs + (kt & 1) * XBS;
#pragma unroll
        for (int ks = 0; ks < 4; ++ks) {
            int ka = ks * 8 + t4;
#pragma unroll
            for (int mt = 0; mt < 2; ++mt) {
                int base = (wm * 32 + mt * 16 + gid) * XAP + ka;
                unsigned a0 = __float_as_uint(A[base]);
                unsigned a1 = __float_as_uint(A[base + 8 * XAP]);
                unsigned a2 = __float_as_uint(A[base + 4]);
                unsigned a3 = __float_as_uint(A[base + 8 * XAP + 4]);
#pragma unroll
                for (int nt = 0; nt < 4; ++nt) {
                    unsigned b0 = __float_as_uint(B[ka * XBP + wn * 32 + nt * 8 + gid]);
                    unsigned b1 = __float_as_uint(B[(ka + 4) * XBP + wn * 32 + nt * 8 + gid]);
                    mma8(acc[mt][nt], a0, a1, a2, a3, b0, b1);
                }
            }
        }
        __syncthreads();
        if (kt < 15) {
            float* A1 = As + ((kt + 1) & 1) * XAS;
            float* B1 = Bs + ((kt + 1) & 1) * XBS;
#pragma unroll
            for (int q = 0; q < 4; ++q) {
                float4 sv;
                sv.x = f2tf(av[q].x); sv.y = f2tf(av[q].y);
                sv.z = f2tf(av[q].z); sv.w = f2tf(av[q].w);
                *(float4*)(A1 + ar * XAP + ak + q * 4) = sv;
            }
            B1[(bk + 0) * XBP + bn] = f2tf(bv[0].x);
            B1[(bk + 1) * XBP + bn] = f2tf(bv[0].y);
            B1[(bk + 2) * XBP + bn] = f2tf(bv[0].z);
            B1[(bk + 3) * XBP + bn] = f2tf(bv[0].w);
            B1[(16 + bk + 0) * XBP + bn] = f2tf(bv[1].x);
            B1[(16 + bk + 1) * XBP + bn] = f2tf(bv[1].y);
            B1[(16 + bk + 2) * XBP + bn] = f2tf(bv[1].z);
            B1[(16 + bk + 3) * XBP + bn] = f2tf(bv[1].w);
            __syncthreads();
        }
    }

#pragma unroll
    for (int nt = 0; nt < 4; ++nt) {
        int col = n0 + wn * 32 + nt * 8 + 2 * t4;
        float b0 = bi[col] + bh[col];
        float b1 = bi[col + 1] + bh[col + 1];
#pragma unroll
        for (int mt = 0; mt < 2; ++mt) {
            int r0 = m0 + wm * 32 + mt * 16 + gid;
            float2 v0 = {acc[mt][nt][0] + b0, acc[mt][nt][1] + b1};
            float2 v1 = {acc[mt][nt][2] + b0, acc[mt][nt][3] + b1};
            *(float2*)&d_Xp[d][r0][col]     = v0;
            *(float2*)&d_Xp[d][r0 + 8][col] = v1;
        }
    }
}

// ---------------- Pt precompute (unchanged) ----------------
__global__ void __launch_bounds__(256, 2) p_kernel(
    const float* __restrict__ Wih_f, const float* __restrict__ Wih_b,
    const float* __restrict__ Mv_f,  const float* __restrict__ Mv_b)
{
    const int d = blockIdx.z;
    const float* W  = d ? Wih_b : Wih_f;
    const float* Mv = d ? Mv_b : Mv_f;
    const int n0 = blockIdx.x * 64;
    const int m0 = blockIdx.y * 64;

    __shared__ float As[8][68], Bs[8][68];
    const int tid = threadIdx.x;
    const int ty = tid >> 4, tx = tid & 15;

    float acc[4][4];
#pragma unroll
    for (int r = 0; r < 4; ++r)
#pragma unroll
        for (int c = 0; c < 4; ++c) acc[r][c] = 0.0f;

    for (int k0 = 0; k0 < 304; k0 += 8) {
        __syncthreads();
#pragma unroll
        for (int i = 0; i < 2; ++i) {
            int idx = i * 256 + tid;
            int r = idx & 63, kk = idx >> 6;
            int k = k0 + kk;
            As[kk][r] = (k < MS) ? W[(size_t)(m0 + r) * INW + 512 + k] : 0.0f;
            Bs[kk][r] = (k < MS && n0 + r < MS) ? Mv[(size_t)k * MS + n0 + r] : 0.0f;
        }
        __syncthreads();
#pragma unroll
        for (int kk = 0; kk < 8; ++kk) {
            float a[4], b[4];
#pragma unroll
            for (int r = 0; r < 4; ++r) a[r] = As[kk][ty * 4 + r];
#pragma unroll
            for (int c = 0; c < 4; ++c) b[c] = Bs[kk][tx * 4 + c];
#pragma unroll
            for (int r = 0; r < 4; ++r)
#pragma unroll
                for (int c = 0; c < 4; ++c) acc[r][c] += a[r] * b[c];
        }
    }
#pragma unroll
    for (int r = 0; r < 4; ++r)
#pragma unroll
        for (int c = 0; c < 4; ++c)
            d_Pt[d][m0 + ty * 4 + r][n0 + tx * 4 + c] = acc[r][c];
}

// ---------------- split barrier: arrive + producer-subset polls ----------
__device__ __forceinline__ void arrive(unsigned ep) {
    __syncthreads();
    if (threadIdx.x == 0) st_rel_exch(&d_flag[blockIdx.x << 5], ep);
}
// poll flags [dbase+lo, dbase+lo+cnt) with threads 0..cnt-1
__device__ __forceinline__ void pollr(unsigned ep, int dbase, int lo, int cnt) {
    if ((int)threadIdx.x < cnt) {
        int spins = 0;
        while (ld_acq(&d_flag[(dbase + lo + (int)threadIdx.x) << 5]) < ep) {
            if (++spins > 512) __nanosleep(32);
        }
    }
}

// ---------------- cp.async chunk staging (256 threads) ----------------
__device__ __forceinline__ void stage_h(unsigned abase, int c, int d, int rp, int tid) {
    const float* hb = &d_hbuf[d][rp][0][0];
#pragma unroll
    for (int q = 0; q < 8; ++q) {
        int idx = q * 256 + tid;
        int row = idx >> 5, kq = idx & 31;
        cpa16(abase + (unsigned)(row * PIT + kq * 4) * 4u, hb + row * HH + c * 128 + kq * 4);
    }
}
__device__ __forceinline__ void stage_e(unsigned abase, int c, int d, int tid) {
    const float* eb = &d_expl[d][0][0];
    if (c < 2) {
#pragma unroll
        for (int q = 0; q < 8; ++q) {
            int idx = q * 256 + tid;
            int row = idx >> 5, kq = idx & 31;
            cpa16(abase + (unsigned)(row * PIT + kq * 4) * 4u, eb + row * 320 + c * 128 + kq * 4);
        }
    } else {
#pragma unroll
        for (int q = 0; q < 4; ++q) {
            int idx = q * 256 + tid;
            int row = idx >> 4, kq = idx & 15;
            cpa16(abase + (unsigned)(row * PIT + kq * 4) * 4u, eb + row * 320 + 256 + kq * 4);
        }
    }
}

// ---------------- MMA over one staged chunk ----------------
template <int KS>
__device__ __forceinline__ void mma_chunk(const float* A, const float* Bq, int kbase,
    float* d0, float* d1, float* dL, int am, int t4, int g0, int gid, bool aux)
{
#pragma unroll
    for (int ks = 0; ks < KS; ++ks) {
        int ka = ks * 8 + t4;
        unsigned a0 = __float_as_uint(A[am + ka]);
        unsigned a1 = __float_as_uint(A[am + 8 * PIT + ka]);
        unsigned a2 = __float_as_uint(A[am + ka + 4]);
        unsigned a3 = __float_as_uint(A[am + 8 * PIT + ka + 4]);
        const float* B0 = Bq + (kbase + ka) * 40;
        unsigned b0 = __float_as_uint(B0[g0 * 8 + gid]);
        unsigned b1 = __float_as_uint(B0[160 + g0 * 8 + gid]);
        mma8(d0, a0, a1, a2, a3, b0, b1);
        unsigned b2 = __float_as_uint(B0[(g0 + 1) * 8 + gid]);
        unsigned b3 = __float_as_uint(B0[160 + (g0 + 1) * 8 + gid]);
        mma8(d1, a0, a1, a2, a3, b2, b3);
        if (aux) {
            unsigned b4 = __float_as_uint(B0[32 + gid]);
            unsigned b5 = __float_as_uint(B0[160 + 32 + gid]);
            mma8(dL, a0, a1, a2, a3, b4, b5);
        }
    }
}

// ---------------- persistent recurrence: 256 threads / 8 warps ----------
__global__ void __launch_bounds__(256, 1) rnn_persist(
    const float* __restrict__ Whh_f, const float* __restrict__ Whh_b,
    const float* __restrict__ Mk_f,  const float* __restrict__ Mk_b,
    const int* __restrict__ lens,
    float* __restrict__ out)
{
    extern __shared__ float shm[];
    __shared__ float c_s[512];
    __shared__ float S_s[64];
    __shared__ float g_s[64 * 33];

    const int blk = blockIdx.x;
    const int d   = blk >> 6;
    const int j   = blk & 63;
    const int dbase = d << 6;
    const float* Whh = d ? Whh_b : Whh_f;
    const float* Mk  = d ? Mk_b : Mk_f;

    const int tid  = threadIdx.x;
    const int w    = tid >> 5;
    const int lane = tid & 31;
    const int gid  = lane >> 2, t4 = lane & 3;
    const int mtile = w & 3, g0 = (w >> 2) * 2;
    const bool auxH = (g0 == 0);      // h-phase aux (logits) on warps 0-3
    const bool auxE = (g0 == 2);      // expl-phase aux (S-sum) on warps 4-7
    const int row0 = mtile * 16 + gid, row1 = row0 + 8;
    const int am   = row0 * PIT;
    const int cA   = g0 * 512 + j * 8 + 2 * t4;

    const int s0 = (j * MS) >> 6, s1 = ((j + 1) * MS) >> 6;
    const int scnt = s1 - s0;

    const unsigned ab0 = (unsigned)__cvta_generic_to_shared(shm + BQ_F);
    const unsigned ab1 = ab0 + ABUF * 4u;
    float* A0 = shm + BQ_F;
    float* A1 = A0 + ABUF;

    // one-time: pack resident B to tf32, pitch 40.
    for (int idx = tid; idx < 832 * 40; idx += 256) {
        int k = idx / 40, n = idx - k * 40;
        float v;
        if (n < 32) {
            int ncol = (n >> 3) * 512 + j * 8 + (n & 7);
            v = (k < 512) ? Whh[(size_t)ncol * HH + k] : d_Pt[d][ncol][k - 512];
        } else {
            int sl = n - 32;
            if (k < 512) v = (sl < scnt) ? Mk[(size_t)(s0 + sl) * HH + k] : 0.0f;
            else         v = 1.0f;
        }
        shm[k * 40 + n] = f2tf(v);
    }
    for (int i = tid; i < 512; i += 256) c_s[i] = 0.0f;
    __syncthreads();

    float xg[8];
    {
        const float* xp = &d_Xp[d][0][0];
        float2 v;
        v = __ldcs((const float2*)(xp + (size_t)row0 * G4 + cA));       xg[0]=v.x; xg[1]=v.y;
        v = __ldcs((const float2*)(xp + (size_t)row1 * G4 + cA));       xg[2]=v.x; xg[3]=v.y;
        v = __ldcs((const float2*)(xp + (size_t)row0 * G4 + cA + 512)); xg[4]=v.x; xg[5]=v.y;
        v = __ldcs((const float2*)(xp + (size_t)row1 * G4 + cA + 512)); xg[6]=v.x; xg[7]=v.y;
    }

    for (int t = 0; t < TT; ++t) {
        const int rp = t & 1, wp = rp ^ 1;
        const unsigned epH = 2u * t - 1u;   // used only when t>0
        const unsigned epE = 2u * t;

        float aG0[4] = {xg[0], xg[1], xg[2], xg[3]};
        float aG1[4] = {xg[4], xg[5], xg[6], xg[7]};
        float aL[4]  = {0.0f, 0.0f, 0.0f, 0.0f};

        if (t > 0) {
            // ---- h part: chunk c produced by blocks 16c..16c+15 ----
            pollr(epH, dbase, 0, 32);          // chunks 0 & 1 producers
            __syncthreads();
            stage_h(ab0, 0, d, rp, tid); CPA_COMMIT();
            stage_h(ab1, 1, d, rp, tid); CPA_COMMIT();
#pragma unroll 1
            for (int c = 0; c < 4; ++c) {
                if (c < 3) cpa_wait<1>(); else cpa_wait<0>();
                __syncthreads();
                if (c < 2) pollr(epH, dbase, 16 * (c + 2), 16);  // hide behind MMA
                mma_chunk<16>((c & 1) ? A1 : A0, shm, c * 128,
                              aG0, aG1, aL, am, t4, g0, gid, auxH);
                if (c < 2) {
                    __syncthreads();
                    stage_h((c & 1) ? ab1 : ab0, c + 2, d, rp, tid);
                    CPA_COMMIT();
                }
            }
            // exp + expl store (tf32-rounded), warps 0-3
            if (auxH) {
                float e0 = f2tf(__expf(aL[0])), e1 = f2tf(__expf(aL[1]));
                float e2 = f2tf(__expf(aL[2])), e3 = f2tf(__expf(aL[3]));
                int sl0 = 2 * t4, sl1 = sl0 + 1;
                if (sl0 < scnt) {
                    d_expl[d][row0][s0 + sl0] = e0;
                    d_expl[d][row1][s0 + sl0] = e2;
                }
                if (sl1 < scnt) {
                    d_expl[d][row0][s0 + sl1] = e1;
                    d_expl[d][row1][s0 + sl1] = e3;
                }
            }
            arrive(epE);

            // ---- expl part: chunk producers [0,28) / [27,55) / [54,64) ----
            {   // concurrent polls for chunks 0 and 1
                int f = -1;
                if (tid < 28) f = tid;                       // chunk 0
                else if (tid >= 32 && tid < 60) f = tid - 5; // chunk 1: 27..54
                if (f >= 0) {
                    int spins = 0;
                    while (ld_acq(&d_flag[(dbase + f) << 5]) < epE) {
                        if (++spins > 512) __nanosleep(32);
                    }
                }
            }
            __syncthreads();
            stage_e(ab0, 0, d, tid); CPA_COMMIT();
            stage_e(ab1, 1, d, tid); CPA_COMMIT();
            float aE0[4] = {0,0,0,0}, aE1[4] = {0,0,0,0};
            float SL[4]  = {0,0,0,0};
#pragma unroll 1
            for (int c = 0; c < 3; ++c) {
                if (c < 2) cpa_wait<1>(); else cpa_wait<0>();
                __syncthreads();
                if (c == 0) pollr(epE, dbase, 54, 10);       // chunk 2, hidden
                if (c < 2)
                    mma_chunk<16>((c & 1) ? A1 : A0, shm, 512 + c * 128,
                                  aE0, aE1, SL, am, t4, g0, gid, auxE);
                else
                    mma_chunk<8>(A0, shm, 512 + 256,
                                 aE0, aE1, SL, am, t4, g0, gid, auxE);
                if (c == 0) {
                    __syncthreads();
                    stage_e(ab0, 2, d, tid); CPA_COMMIT();
                }
            }
            if (auxE && t4 == 0) {
                S_s[row0] = 1.0f / SL[0];
                S_s[row1] = 1.0f / SL[2];
            }
            __syncthreads();
            float si0 = S_s[row0], si1 = S_s[row1];
            aG0[0] += aE0[0] * si0; aG0[1] += aE0[1] * si0;
            aG0[2] += aE0[2] * si1; aG0[3] += aE0[3] * si1;
            aG1[0] += aE1[0] * si0; aG1[1] += aE1[1] * si0;
            aG1[2] += aE1[2] * si1; aG1[3] += aE1[3] * si1;
        }

        __syncthreads();
        {
            int cl0 = g0 * 8 + 2 * t4, cl1 = cl0 + 8;
            g_s[row0 * 33 + cl0] = aG0[0]; g_s[row0 * 33 + cl0 + 1] = aG0[1];
            g_s[row1 * 33 + cl0] = aG0[2]; g_s[row1 * 33 + cl0 + 1] = aG0[3];
            g_s[row0 * 33 + cl1] = aG1[0]; g_s[row0 * 33 + cl1 + 1] = aG1[1];
            g_s[row1 * 33 + cl1] = aG1[2]; g_s[row1 * 33 + cl1 + 1] = aG1[3];
        }
        __syncthreads();

#pragma unroll
        for (int pi = 0; pi < 2; ++pi) {
            int p = tid + pi * 256;
            int b = p >> 3, uu = p & 7;
            float gi = g_s[b * 33 + uu];
            float gf = g_s[b * 33 + 8 + uu];
            float gg = g_s[b * 33 + 16 + uu];
            float go = g_s[b * 33 + 24 + uu];
            float iv = 1.0f / (1.0f + __expf(-gi));
            float fv = 1.0f / (1.0f + __expf(-gf));
            float gv = tanhf(gg);
            float ov = 1.0f / (1.0f + __expf(-go));
            float c = fv * c_s[p] + iv * gv;
            c_s[p] = c;
            float h = f2tf(ov * tanhf(c));
            d_hbuf[d][wp][b][j * 8 + uu] = h;
            int torig = d ? (TT - 1 - t) : t;
            float mval = (torig < lens[b]) ? h : 0.0f;
            out[((size_t)b * TT + torig) * 1024 + d * 512 + j * 8 + uu] = mval;
        }

        {
            int tn = (t + 1 < TT) ? (t + 1) : t;
            const float* xp = &d_Xp[d][(size_t)tn * BB][0];
            float2 v;
            v = __ldcs((const float2*)(xp + (size_t)row0 * G4 + cA));       xg[0]=v.x; xg[1]=v.y;
            v = __ldcs((const float2*)(xp + (size_t)row1 * G4 + cA));       xg[2]=v.x; xg[3]=v.y;
            v = __ldcs((const float2*)(xp + (size_t)row0 * G4 + cA + 512)); xg[4]=v.x; xg[5]=v.y;
            v = __ldcs((const float2*)(xp + (size_t)row1 * G4 + cA + 512)); xg[6]=v.x; xg[7]=v.y;
        }
        arrive(2u * t + 1u);
    }
}

// ---------------- launch ----------------
extern "C" void kernel_launch(void* const* d_in, const int* in_sizes, int n_in,
                              void* d_out, int out_size) {
    const float* seqs   = (const float*)d_in[0];
    const int*   ln     = (const int*)d_in[1];
    const float* Wih_f  = (const float*)d_in[2];
    const float* Whh_f  = (const float*)d_in[3];
    const float* bih_f  = (const float*)d_in[4];
    const float* bhh_f  = (const float*)d_in[5];
    const float* Mk_f   = (const float*)d_in[6];
    const float* Mv_f   = (const float*)d_in[7];
    const float* Wih_b  = (const float*)d_in[8];
    const float* Whh_b  = (const float*)d_in[9];
    const float* bih_b  = (const float*)d_in[10];
    const float* bhh_b  = (const float*)d_in[11];
    const float* Mk_b   = (const float*)d_in[12];
    const float* Mv_b   = (const float*)d_in[13];
    float* out = (float*)d_out;

    cudaFuncSetAttribute(rnn_persist,
                         cudaFuncAttributeMaxDynamicSharedMemorySize, DYN_BYTES);
    cudaFuncSetAttribute(xproj_mma,
                         cudaFuncAttributeMaxDynamicSharedMemorySize, XP_SMEM);

    reset_kernel<<<64, 256>>>();
    xproj_mma<<<dim3(32, 256, 2), 256, XP_SMEM>>>(seqs, Wih_f, Wih_b,
                                                  bih_f, bhh_f, bih_b, bhh_b);
    p_kernel<<<dim3(5, 32, 2), 256>>>(Wih_f, Wih_b, Mv_f, Mv_b);
    rnn_persist<<<NBLK, 256, DYN_BYTES>>>(Whh_f, Whh_b, Mk_f, Mk_b, ln, out);
}

// round 16
// speedup vs baseline: 1.0590x; 1.0590x over previous
#include <cuda_runtime.h>

#define TT   512
#define BB   64
#define HH   512
#define G4   2048
#define MS   300
#define INW  812
#define NBLK 128
#define BQ_F 33280              /* 832 k x 40 n resident weight smem (floats) */
#define PIT  132                /* A-chunk row pitch (floats)                 */
#define ABUF (64*PIT)           /* floats per A chunk buffer                  */
#define DYN_BYTES ((BQ_F + 2*ABUF)*4)

#define XAP  36
#define XBP  72
#define XAS  (128*XAP)
#define XBS  (32*XBP)
#define XP_SMEM ((2*XAS + 2*XBS)*4)

// ---------------- device scratch ----------------
__device__ float d_Xp[2][TT * BB][G4];
__device__ float d_hbuf[2][2][BB][HH];      // h, tf32-rounded at producer
__device__ float d_expl[2][BB][320];        // exp(logits), batch-major, tf32, zero-padded
__device__ float d_Pt[2][G4][320];
__device__ unsigned d_flag[NBLK * 32];      // per-block epoch flags, 128B apart

__global__ void reset_kernel() {
    int i = blockIdx.x * blockDim.x + threadIdx.x;
    int n = gridDim.x * blockDim.x;
    for (int x = i; x < NBLK * 32; x += n) d_flag[x] = 0u;
    float* e = &d_expl[0][0][0];
    for (int x = i; x < 2 * BB * 320; x += n) e[x] = 0.0f;
}

__device__ __forceinline__ float f2tf(float f) {
    unsigned u; asm("cvt.rna.tf32.f32 %0, %1;" : "=r"(u) : "f"(f));
    return __uint_as_float(u);
}
__device__ __forceinline__ void mma8(float* d, unsigned a0, unsigned a1,
    unsigned a2, unsigned a3, unsigned b0, unsigned b1) {
    asm volatile("mma.sync.aligned.m16n8k8.row.col.f32.tf32.tf32.f32 "
        "{%0,%1,%2,%3},{%4,%5,%6,%7},{%8,%9},{%0,%1,%2,%3};"
        : "+f"(d[0]), "+f"(d[1]), "+f"(d[2]), "+f"(d[3])
        : "r"(a0), "r"(a1), "r"(a2), "r"(a3), "r"(b0), "r"(b1));
}
__device__ __forceinline__ void cpa16(unsigned dst, const void* src) {
    asm volatile("cp.async.cg.shared.global [%0], [%1], 16;" :: "r"(dst), "l"(src));
}
#define CPA_COMMIT() asm volatile("cp.async.commit_group;")
template <int N> __device__ __forceinline__ void cpa_wait() {
    asm volatile("cp.async.wait_group %0;" :: "n"(N));
}
__device__ __forceinline__ unsigned ld_acq(const unsigned* p) {
    unsigned v;
    asm volatile("ld.acquire.gpu.global.u32 %0, [%1];" : "=r"(v) : "l"(p));
    return v;
}
__device__ __forceinline__ void st_rel_exch(unsigned* p, unsigned v) {
    unsigned old;
    asm volatile("atom.release.gpu.global.exch.b32 %0, [%1], %2;"
                 : "=r"(old) : "l"(p), "r"(v) : "memory");
}
__device__ __forceinline__ void bar_pair(int bid) {
    asm volatile("bar.sync %0, 64;" :: "r"(bid) : "memory");
}

// ---------------- xproj via tf32 MMA (unchanged) ----------------
__global__ void __launch_bounds__(256, 1) xproj_mma(
    const float* __restrict__ seqs,
    const float* __restrict__ Wih_f, const float* __restrict__ Wih_b,
    const float* __restrict__ bih_f, const float* __restrict__ bhh_f,
    const float* __restrict__ bih_b, const float* __restrict__ bhh_b)
{
    extern __shared__ float xs[];
    float* As = xs;
    float* Bs = xs + 2 * XAS;

    const int d  = blockIdx.z;
    const float* W  = d ? Wih_b : Wih_f;
    const float* bi = d ? bih_b : bih_f;
    const float* bh = d ? bhh_b : bhh_f;
    const int n0 = blockIdx.x * 64;
    const int m0 = blockIdx.y * 128;

    const int tid  = threadIdx.x;
    const int w    = tid >> 5, lane = tid & 31;
    const int gid  = lane >> 2, t4 = lane & 3;
    const int wm   = w & 3, wn = w >> 2;

    const int ar = tid >> 1;
    const int ak = (tid & 1) * 16;
    const int grow = m0 + ar;
    const int att  = grow >> 6;
    const int abb  = grow & 63;
    const int tsrc = d ? (TT - 1 - att) : att;
    const float* aptr = seqs + ((size_t)abb * TT + tsrc) * HH + ak;

    const int bn = tid >> 2;
    const int bk = (tid & 3) * 4;
    const float* bptr = W + (size_t)(n0 + bn) * INW + bk;

    float acc[2][4][4];
#pragma unroll
    for (int mt = 0; mt < 2; ++mt)
#pragma unroll
        for (int nt = 0; nt < 4; ++nt)
#pragma unroll
            for (int i = 0; i < 4; ++i) acc[mt][nt][i] = 0.0f;

    float4 av[4], bv[2];
#pragma unroll
    for (int q = 0; q < 4; ++q) av[q] = *(const float4*)(aptr + q * 4);
    bv[0] = *(const float4*)(bptr);
    bv[1] = *(const float4*)(bptr + 16);
    {
        float* A0 = As; float* B0 = Bs;
#pragma unroll
        for (int q = 0; q < 4; ++q) {
            float4 sv;
            sv.x = f2tf(av[q].x); sv.y = f2tf(av[q].y);
            sv.z = f2tf(av[q].z); sv.w = f2tf(av[q].w);
            *(float4*)(A0 + ar * XAP + ak + q * 4) = sv;
        }
        B0[(bk + 0) * XBP + bn] = f2tf(bv[0].x);
        B0[(bk + 1) * XBP + bn] = f2tf(bv[0].y);
        B0[(bk + 2) * XBP + bn] = f2tf(bv[0].z);
        B0[(bk + 3) * XBP + bn] = f2tf(bv[0].w);
        B0[(16 + bk + 0) * XBP + bn] = f2tf(bv[1].x);
        B0[(16 + bk + 1) * XBP + bn] = f2tf(bv[1].y);
        B0[(16 + bk + 2) * XBP + bn] = f2tf(bv[1].z);
        B0[(16 + bk + 3) * XBP + bn] = f2tf(bv[1].w);
    }
    __syncthreads();

#pragma unroll 1
    for (int kt = 0; kt < 16; ++kt) {
        if (kt < 15) {
            int k0 = (kt + 1) * 32;
#pragma unroll
            for (int q = 0; q < 4; ++q) av[q] = *(const float4*)(aptr + k0 + q * 4);
            bv[0] = *(const float4*)(bptr + k0);
            bv[1] = *(const float4*)(bptr + k0 + 16);
        }
        const float* A = As + (kt & 1) * XAS;
        const float* B = Bs + (kt & 1) * XBS;
#pragma unroll
        for (int ks = 0; ks < 4; ++ks) {
            int ka = ks * 8 + t4;
#pragma unroll
            for (int mt = 0; mt < 2; ++mt) {
                int base = (wm * 32 + mt * 16 + gid) * XAP + ka;
                unsigned a0 = __float_as_uint(A[base]);
                unsigned a1 = __float_as_uint(A[base + 8 * XAP]);
                unsigned a2 = __float_as_uint(A[base + 4]);
                unsigned a3 = __float_as_uint(A[base + 8 * XAP + 4]);
#pragma unroll
                for (int nt = 0; nt < 4; ++nt) {
                    unsigned b0 = __float_as_uint(B[ka * XBP + wn * 32 + nt * 8 + gid]);
                    unsigned b1 = __float_as_uint(B[(ka + 4) * XBP + wn * 32 + nt * 8 + gid]);
                    mma8(acc[mt][nt], a0, a1, a2, a3, b0, b1);
                }
            }
        }
        __syncthreads();
        if (kt < 15) {
            float* A1 = As + ((kt + 1) & 1) * XAS;
            float* B1 = Bs + ((kt + 1) & 1) * XBS;
#pragma unroll
            for (int q = 0; q < 4; ++q) {
                float4 sv;
                sv.x = f2tf(av[q].x); sv.y = f2tf(av[q].y);
                sv.z = f2tf(av[q].z); sv.w = f2tf(av[q].w);
                *(float4*)(A1 + ar * XAP + ak + q * 4) = sv;
            }
            B1[(bk + 0) * XBP + bn] = f2tf(bv[0].x);
            B1[(bk + 1) * XBP + bn] = f2tf(bv[0].y);
            B1[(bk + 2) * XBP + bn] = f2tf(bv[0].z);
            B1[(bk + 3) * XBP + bn] = f2tf(bv[0].w);
            B1[(16 + bk + 0) * XBP + bn] = f2tf(bv[1].x);
            B1[(16 + bk + 1) * XBP + bn] = f2tf(bv[1].y);
            B1[(16 + bk + 2) * XBP + bn] = f2tf(bv[1].z);
            B1[(16 + bk + 3) * XBP + bn] = f2tf(bv[1].w);
            __syncthreads();
        }
    }

#pragma unroll
    for (int nt = 0; nt < 4; ++nt) {
        int col = n0 + wn * 32 + nt * 8 + 2 * t4;
        float b0 = bi[col] + bh[col];
        float b1 = bi[col + 1] + bh[col + 1];
#pragma unroll
        for (int mt = 0; mt < 2; ++mt) {
            int r0 = m0 + wm * 32 + mt * 16 + gid;
            float2 v0 = {acc[mt][nt][0] + b0, acc[mt][nt][1] + b1};
            float2 v1 = {acc[mt][nt][2] + b0, acc[mt][nt][3] + b1};
            *(float2*)&d_Xp[d][r0][col]     = v0;
            *(float2*)&d_Xp[d][r0 + 8][col] = v1;
        }
    }
}

// ---------------- Pt precompute (unchanged) ----------------
__global__ void __launch_bounds__(256, 2) p_kernel(
    const float* __restrict__ Wih_f, const float* __restrict__ Wih_b,
    const float* __restrict__ Mv_f,  const float* __restrict__ Mv_b)
{
    const int d = blockIdx.z;
    const float* W  = d ? Wih_b : Wih_f;
    const float* Mv = d ? Mv_b : Mv_f;
    const int n0 = blockIdx.x * 64;
    const int m0 = blockIdx.y * 64;

    __shared__ float As[8][68], Bs[8][68];
    const int tid = threadIdx.x;
    const int ty = tid >> 4, tx = tid & 15;

    float acc[4][4];
#pragma unroll
    for (int r = 0; r < 4; ++r)
#pragma unroll
        for (int c = 0; c < 4; ++c) acc[r][c] = 0.0f;

    for (int k0 = 0; k0 < 304; k0 += 8) {
        __syncthreads();
#pragma unroll
        for (int i = 0; i < 2; ++i) {
            int idx = i * 256 + tid;
            int r = idx & 63, kk = idx >> 6;
            int k = k0 + kk;
            As[kk][r] = (k < MS) ? W[(size_t)(m0 + r) * INW + 512 + k] : 0.0f;
            Bs[kk][r] = (k < MS && n0 + r < MS) ? Mv[(size_t)k * MS + n0 + r] : 0.0f;
        }
        __syncthreads();
#pragma unroll
        for (int kk = 0; kk < 8; ++kk) {
            float a[4], b[4];
#pragma unroll
            for (int r = 0; r < 4; ++r) a[r] = As[kk][ty * 4 + r];
#pragma unroll
            for (int c = 0; c < 4; ++c) b[c] = Bs[kk][tx * 4 + c];
#pragma unroll
            for (int r = 0; r < 4; ++r)
#pragma unroll
                for (int c = 0; c < 4; ++c) acc[r][c] += a[r] * b[c];
        }
    }
#pragma unroll
    for (int r = 0; r < 4; ++r)
#pragma unroll
        for (int c = 0; c < 4; ++c)
            d_Pt[d][m0 + ty * 4 + r][n0 + tx * 4 + c] = acc[r][c];
}

// ---------------- barrier primitives ----------------
__device__ __forceinline__ void wait_all(unsigned ep, int dbase) {
    if (threadIdx.x < 64) {
        int spins = 0;
        while (ld_acq(&d_flag[(dbase + (int)threadIdx.x) << 5]) < ep) {
            if (++spins > 512) __nanosleep(32);
        }
    }
    __syncthreads();
}
__device__ __forceinline__ void arrive(unsigned ep) {
    __syncthreads();
    if (threadIdx.x == 0) st_rel_exch(&d_flag[blockIdx.x << 5], ep);
}

// ---------------- per-pair cp.async staging (64 threads, own 16 rows) ------
__device__ __forceinline__ void stage_h_pair(unsigned abase, int c, int dd, int rp,
                                             int mtile, int pt) {
    const float* hb = &d_hbuf[dd][rp][0][0];
#pragma unroll
    for (int q = 0; q < 8; ++q) {
        int idx = q * 64 + pt;
        int row = 16 * mtile + (idx >> 5), kq = idx & 31;
        cpa16(abase + (unsigned)(row * PIT + kq * 4) * 4u,
              hb + row * HH + c * 128 + kq * 4);
    }
}
__device__ __forceinline__ void stage_e_pair(unsigned abase, int c, int dd,
                                             int mtile, int pt) {
    const float* eb = &d_expl[dd][0][0];
    if (c < 2) {
#pragma unroll
        for (int q = 0; q < 8; ++q) {
            int idx = q * 64 + pt;
            int row = 16 * mtile + (idx >> 5), kq = idx & 31;
            cpa16(abase + (unsigned)(row * PIT + kq * 4) * 4u,
                  eb + row * 320 + c * 128 + kq * 4);
        }
    } else {
#pragma unroll
        for (int q = 0; q < 4; ++q) {
            int idx = q * 64 + pt;
            int row = 16 * mtile + (idx >> 4), kq = idx & 15;
            cpa16(abase + (unsigned)(row * PIT + kq * 4) * 4u,
                  eb + row * 320 + 256 + kq * 4);
        }
    }
}

// ---------------- MMA over one staged chunk ----------------
template <int KS>
__device__ __forceinline__ void mma_chunk(const float* A, const float* Bq, int kbase,
    float* d0, float* d1, float* dL, int am, int t4, int g0, int gid, bool aux)
{
#pragma unroll
    for (int ks = 0; ks < KS; ++ks) {
        int ka = ks * 8 + t4;
        unsigned a0 = __float_as_uint(A[am + ka]);
        unsigned a1 = __float_as_uint(A[am + 8 * PIT + ka]);
        unsigned a2 = __float_as_uint(A[am + ka + 4]);
        unsigned a3 = __float_as_uint(A[am + 8 * PIT + ka + 4]);
        const float* B0 = Bq + (kbase + ka) * 40;
        unsigned b0 = __float_as_uint(B0[g0 * 8 + gid]);
        unsigned b1 = __float_as_uint(B0[160 + g0 * 8 + gid]);
        mma8(d0, a0, a1, a2, a3, b0, b1);
        unsigned b2 = __float_as_uint(B0[(g0 + 1) * 8 + gid]);
        unsigned b3 = __float_as_uint(B0[160 + (g0 + 1) * 8 + gid]);
        mma8(d1, a0, a1, a2, a3, b2, b3);
        if (aux) {
            unsigned b4 = __float_as_uint(B0[32 + gid]);
            unsigned b5 = __float_as_uint(B0[160 + 32 + gid]);
            mma8(dL, a0, a1, a2, a3, b4, b5);
        }
    }
}

// ---------------- persistent recurrence: pair-pipelined ----------------
__global__ void __launch_bounds__(256, 1) rnn_persist(
    const float* __restrict__ Whh_f, const float* __restrict__ Whh_b,
    const float* __restrict__ Mk_f,  const float* __restrict__ Mk_b,
    const int* __restrict__ lens,
    float* __restrict__ out)
{
    extern __shared__ float shm[];
    __shared__ float c_s[512];
    __shared__ float S_s[64];
    __shared__ float g_s[64 * 33];

    const int blk = blockIdx.x;
    const int d   = blk >> 6;
    const int j   = blk & 63;
    const int dbase = d << 6;
    const float* Whh = d ? Whh_b : Whh_f;
    const float* Mk  = d ? Mk_b : Mk_f;

    const int tid  = threadIdx.x;
    const int w    = tid >> 5;
    const int lane = tid & 31;
    const int gid  = lane >> 2, t4 = lane & 3;
    const int mtile = w & 3, g0 = (w >> 2) * 2;
    const bool auxH = (g0 == 0);
    const bool auxE = (g0 == 2);
    const int bid  = 1 + mtile;                 // named barrier per pair
    const int pt   = lane + ((w >> 2) << 5);    // 0..63 within pair
    const int row0 = mtile * 16 + gid, row1 = row0 + 8;
    const int am   = row0 * PIT;
    const int cA   = g0 * 512 + j * 8 + 2 * t4;

    const int s0 = (j * MS) >> 6, s1 = ((j + 1) * MS) >> 6;
    const int scnt = s1 - s0;

    const unsigned ab0 = (unsigned)__cvta_generic_to_shared(shm + BQ_F);
    const unsigned ab1 = ab0 + ABUF * 4u;
    float* A0 = shm + BQ_F;
    float* A1 = A0 + ABUF;

    // one-time: pack resident B to tf32, pitch 40.
    for (int idx = tid; idx < 832 * 40; idx += 256) {
        int k = idx / 40, n = idx - k * 40;
        float v;
        if (n < 32) {
            int ncol = (n >> 3) * 512 + j * 8 + (n & 7);
            v = (k < 512) ? Whh[(size_t)ncol * HH + k] : d_Pt[d][ncol][k - 512];
        } else {
            int sl = n - 32;
            if (k < 512) v = (sl < scnt) ? Mk[(size_t)(s0 + sl) * HH + k] : 0.0f;
            else         v = 1.0f;
        }
        shm[k * 40 + n] = f2tf(v);
    }
    for (int i = tid; i < 512; i += 256) c_s[i] = 0.0f;
    __syncthreads();

    float xg[8];
    {
        const float* xp = &d_Xp[d][0][0];
        float2 v;
        v = __ldcs((const float2*)(xp + (size_t)row0 * G4 + cA));       xg[0]=v.x; xg[1]=v.y;
        v = __ldcs((const float2*)(xp + (size_t)row1 * G4 + cA));       xg[2]=v.x; xg[3]=v.y;
        v = __ldcs((const float2*)(xp + (size_t)row0 * G4 + cA + 512)); xg[4]=v.x; xg[5]=v.y;
        v = __ldcs((const float2*)(xp + (size_t)row1 * G4 + cA + 512)); xg[6]=v.x; xg[7]=v.y;
    }

    for (int t = 0; t < TT; ++t) {
        const int rp = t & 1, wp = rp ^ 1;

        float aG0[4] = {xg[0], xg[1], xg[2], xg[3]};
        float aG1[4] = {xg[4], xg[5], xg[6], xg[7]};
        float aL[4]  = {0.0f, 0.0f, 0.0f, 0.0f};

        if (t > 0) {
            // ---- h part: per-pair pipeline over 4 chunks of 128 ----
            wait_all(2u * t - 1u, dbase);
            stage_h_pair(ab0, 0, d, rp, mtile, pt); CPA_COMMIT();
            stage_h_pair(ab1, 1, d, rp, mtile, pt); CPA_COMMIT();
#pragma unroll 1
            for (int c = 0; c < 4; ++c) {
                if (c < 3) cpa_wait<1>(); else cpa_wait<0>();
                bar_pair(bid);
                mma_chunk<16>((c & 1) ? A1 : A0, shm, c * 128,
                              aG0, aG1, aL, am, t4, g0, gid, auxH);
                if (c < 2) {
                    bar_pair(bid);
                    stage_h_pair((c & 1) ? ab1 : ab0, c + 2, d, rp, mtile, pt);
                    CPA_COMMIT();
                }
            }
            // exp + expl store (tf32-rounded), warps 0-3 (own registers only)
            if (auxH) {
                float e0 = f2tf(__expf(aL[0])), e1 = f2tf(__expf(aL[1]));
                float e2 = f2tf(__expf(aL[2])), e3 = f2tf(__expf(aL[3]));
                int sl0 = 2 * t4, sl1 = sl0 + 1;
                if (sl0 < scnt) {
                    d_expl[d][row0][s0 + sl0] = e0;
                    d_expl[d][row1][s0 + sl0] = e2;
                }
                if (sl1 < scnt) {
                    d_expl[d][row0][s0 + sl1] = e1;
                    d_expl[d][row1][s0 + sl1] = e3;
                }
            }
            arrive(2u * t);

            // ---- expl part: per-pair pipeline, chunks 128/128/64 ----
            wait_all(2u * t, dbase);
            stage_e_pair(ab0, 0, d, mtile, pt); CPA_COMMIT();
            stage_e_pair(ab1, 1, d, mtile, pt); CPA_COMMIT();
            float aE0[4] = {0,0,0,0}, aE1[4] = {0,0,0,0};
            float SL[4]  = {0,0,0,0};
#pragma unroll 1
            for (int c = 0; c < 3; ++c) {
                if (c < 2) cpa_wait<1>(); else cpa_wait<0>();
                bar_pair(bid);
                if (c < 2)
                    mma_chunk<16>((c & 1) ? A1 : A0, shm, 512 + c * 128,
                                  aE0, aE1, SL, am, t4, g0, gid, auxE);
                else
                    mma_chunk<8>(A0, shm, 512 + 256,
                                 aE0, aE1, SL, am, t4, g0, gid, auxE);
                if (c == 0) {
                    bar_pair(bid);
                    stage_e_pair(ab0, 2, d, mtile, pt);
                    CPA_COMMIT();
                }
            }
            // auxE warp publishes 1/S for its pair's rows; pair-local sync
            if (auxE && t4 == 0) {
                S_s[row0] = 1.0f / SL[0];
                S_s[row1] = 1.0f / SL[2];
            }
            bar_pair(bid);
            float si0 = S_s[row0], si1 = S_s[row1];
            aG0[0] += aE0[0] * si0; aG0[1] += aE0[1] * si0;
            aG0[2] += aE0[2] * si1; aG0[3] += aE0[3] * si1;
            aG1[0] += aE1[0] * si0; aG1[1] += aE1[1] * si0;
            aG1[2] += aE1[2] * si1; aG1[3] += aE1[3] * si1;
        }

        // gates -> shared; block-wide (cell phase mixes rows across pairs)
        {
            int cl0 = g0 * 8 + 2 * t4, cl1 = cl0 + 8;
            g_s[row0 * 33 + cl0] = aG0[0]; g_s[row0 * 33 + cl0 + 1] = aG0[1];
            g_s[row1 * 33 + cl0] = aG0[2]; g_s[row1 * 33 + cl0 + 1] = aG0[3];
            g_s[row0 * 33 + cl1] = aG1[0]; g_s[row0 * 33 + cl1 + 1] = aG1[1];
            g_s[row1 * 33 + cl1] = aG1[2]; g_s[row1 * 33 + cl1 + 1] = aG1[3];
        }
        __syncthreads();

        float mv[2]; int torig = d ? (TT - 1 - t) : t;
#pragma unroll
        for (int pi = 0; pi < 2; ++pi) {
            int p = tid + pi * 256;
            int b = p >> 3, uu = p & 7;
            float gi = g_s[b * 33 + uu];
            float gf = g_s[b * 33 + 8 + uu];
            float gg = g_s[b * 33 + 16 + uu];
            float go = g_s[b * 33 + 24 + uu];
            float iv = 1.0f / (1.0f + __expf(-gi));
            float fv = 1.0f / (1.0f + __expf(-gf));
            float gv = tanhf(gg);
            float ov = 1.0f / (1.0f + __expf(-go));
            float c = fv * c_s[p] + iv * gv;
            c_s[p] = c;
            float h = f2tf(ov * tanhf(c));
            d_hbuf[d][wp][b][j * 8 + uu] = h;
            mv[pi] = (torig < lens[b]) ? h : 0.0f;
        }

        // EARLY PUBLISH: flag fires before output DRAM stores + Xp prefetch
        arrive(2u * t + 1u);

#pragma unroll
        for (int pi = 0; pi < 2; ++pi) {
            int p = tid + pi * 256;
            int b = p >> 3, uu = p & 7;
            out[((size_t)b * TT + torig) * 1024 + d * 512 + j * 8 + uu] = mv[pi];
        }
        {
            int tn = (t + 1 < TT) ? (t + 1) : t;
            const float* xp = &d_Xp[d][(size_t)tn * BB][0];
            float2 v;
            v = __ldcs((const float2*)(xp + (size_t)row0 * G4 + cA));       xg[0]=v.x; xg[1]=v.y;
            v = __ldcs((const float2*)(xp + (size_t)row1 * G4 + cA));       xg[2]=v.x; xg[3]=v.y;
            v = __ldcs((const float2*)(xp + (size_t)row0 * G4 + cA + 512)); xg[4]=v.x; xg[5]=v.y;
            v = __ldcs((const float2*)(xp + (size_t)row1 * G4 + cA + 512)); xg[6]=v.x; xg[7]=v.y;
        }
    }
}

// ---------------- launch ----------------
extern "C" void kernel_launch(void* const* d_in, const int* in_sizes, int n_in,
                              void* d_out, int out_size) {
    const float* seqs   = (const float*)d_in[0];
    const int*   ln     = (const int*)d_in[1];
    const float* Wih_f  = (const float*)d_in[2];
    const float* Whh_f  = (const float*)d_in[3];
    const float* bih_f  = (const float*)d_in[4];
    const float* bhh_f  = (const float*)d_in[5];
    const float* Mk_f   = (const float*)d_in[6];
    const float* Mv_f   = (const float*)d_in[7];
    const float* Wih_b  = (const float*)d_in[8];
    const float* Whh_b  = (const float*)d_in[9];
    const float* bih_b  = (const float*)d_in[10];
    const float* bhh_b  = (const float*)d_in[11];
    const float* Mk_b   = (const float*)d_in[12];
    const float* Mv_b   = (const float*)d_in[13];
    float* out = (float*)d_out;

    cudaFuncSetAttribute(rnn_persist,
                         cudaFuncAttributeMaxDynamicSharedMemorySize, DYN_BYTES);
    cudaFuncSetAttribute(xproj_mma,
                         cudaFuncAttributeMaxDynamicSharedMemorySize, XP_SMEM);

    reset_kernel<<<64, 256>>>();
    xproj_mma<<<dim3(32, 256, 2), 256, XP_SMEM>>>(seqs, Wih_f, Wih_b,
                                                  bih_f, bhh_f, bih_b, bhh_b);
    p_kernel<<<dim3(5, 32, 2), 256>>>(Wih_f, Wih_b, Mv_f, Mv_b);
    rnn_persist<<<NBLK, 256, DYN_BYTES>>>(Whh_f, Whh_b, Mk_f, Mk_b, ln, out);
}